// round 5
// baseline (speedup 1.0000x reference)
#include <cuda_runtime.h>
#include <cstdint>

#define N_NODES 4096
#define OUTF 256
#define NH 8
#define TI 16
#define JC 32
#define NCHUNK (N_NODES / JC)

typedef unsigned long long u64;

// Scratch (device globals — no allocation allowed)
__device__ float  g_buf[N_NODES * OUTF];      // g = h @ W^T, [n][h*32+f]
__device__ float2 PLC_buf[N_NODES * NH];      // {exp(s_i), exp(0.2 s_i)}
__device__ float2 PRC_buf[N_NODES * NH];      // {exp(s_j), exp(0.2 s_j)}

#define PACK2(d, lo, hi) asm("mov.b64 %0, {%1, %2};" : "=l"(d) : "r"(lo), "r"(hi))
#define UNPACK2(lo, hi, s) asm("mov.b64 {%0, %1}, %2;" : "=r"(lo), "=r"(hi) : "l"(s))
#define FMA2(d, a, b, c) asm("fma.rn.f32x2 %0, %1, %2, %3;" : "=l"(d) : "l"(a), "l"(b), "l"(c))
#define MUL2(d, a, b) asm("mul.rn.f32x2 %0, %1, %2;" : "=l"(d) : "l"(a), "l"(b))
#define LDSV2(a, b, addr) asm volatile("ld.shared.v2.b64 {%0,%1},[%2];" : "=l"(a), "=l"(b) : "r"(addr))

// ---------------------------------------------------------------------------
// Kernel 1: g = h @ W^T   (4096x256 @ 256x256)
// ---------------------------------------------------------------------------
__global__ __launch_bounds__(256) void gemm_kernel(const float* __restrict__ H,
                                                   const float* __restrict__ W) {
    __shared__ float hs[64][32];
    __shared__ float ws[32][68];
    int t  = threadIdx.x;
    int bo = blockIdx.x;
    int bn = blockIdx.y;
    int tx = t & 15, ty = t >> 4;
    float acc[4][4] = {};

    int r = t >> 3, c = (t & 7) << 2;
    for (int k0 = 0; k0 < 256; k0 += 32) {
#pragma unroll
        for (int rr = 0; rr < 64; rr += 32) {
            float4 v = *(const float4*)&H[(bn * 64 + r + rr) * 256 + k0 + c];
            *(float4*)&hs[r + rr][c] = v;
        }
#pragma unroll
        for (int oo = 0; oo < 64; oo += 32) {
            float4 v = *(const float4*)&W[(bo * 64 + r + oo) * 256 + k0 + c];
            ws[c + 0][r + oo] = v.x; ws[c + 1][r + oo] = v.y;
            ws[c + 2][r + oo] = v.z; ws[c + 3][r + oo] = v.w;
        }
        __syncthreads();
#pragma unroll
        for (int k = 0; k < 32; k++) {
            float4 bv = *(const float4*)&ws[k][tx * 4];
            const float* bp = &bv.x;
            float av[4];
#pragma unroll
            for (int i = 0; i < 4; i++) av[i] = hs[ty * 4 + i][k];
#pragma unroll
            for (int i = 0; i < 4; i++)
#pragma unroll
                for (int j = 0; j < 4; j++)
                    acc[i][j] = fmaf(av[i], bp[j], acc[i][j]);
        }
        __syncthreads();
    }
#pragma unroll
    for (int i = 0; i < 4; i++) {
        float4 v = make_float4(acc[i][0], acc[i][1], acc[i][2], acc[i][3]);
        *(float4*)&g_buf[(bn * 64 + ty * 4 + i) * 256 + bo * 64 + tx * 4] = v;
    }
}

// ---------------------------------------------------------------------------
// Kernel 2: per-node scores -> compact {E, F} exponential tables.
// ---------------------------------------------------------------------------
__global__ __launch_bounds__(256) void score_kernel(const float* __restrict__ a) {
    int gw   = (blockIdx.x * 256 + threadIdx.x) >> 5;
    int lane = threadIdx.x & 31;
    if (gw >= N_NODES) return;
    float al = a[lane], ar = a[32 + lane];
#pragma unroll
    for (int h = 0; h < NH; h++) {
        float gv = g_buf[gw * 256 + h * 32 + lane];
        float sl = gv * al, sr = gv * ar;
#pragma unroll
        for (int o = 16; o > 0; o >>= 1) {
            sl += __shfl_xor_sync(0xffffffffu, sl, o);
            sr += __shfl_xor_sync(0xffffffffu, sr, o);
        }
        if (lane == 0) {
            PLC_buf[gw * NH + h] = make_float2(expf(sl), expf(0.2f * sl));
            PRC_buf[gw * NH + h] = make_float2(expf(sr), expf(0.2f * sr));
        }
    }
}

// ---------------------------------------------------------------------------
// Kernel 3: fused masked-softmax attention + aggregation.
// Uniform warps, 3-buffer ring, one __syncthreads per chunk.
// Produce role (per thread, fixed i,h, half of the jj range):
//   w = adj ? max(E_i E_j, F_i F_j) : 0   via one mul.rn.f32x2 + FMNMX.
// Consume role (warp = head, lane = feature): packed f32x2 FMAs, g pipelined
// through register halves, 128-bit broadcast shared loads of w.
// ---------------------------------------------------------------------------
__global__ __launch_bounds__(256, 2) void attn_kernel(const int* __restrict__ adj,
                                                      float* __restrict__ out) {
    __shared__ float w_sh[3][JC][NH][16];   // 48KB exactly; [buf][jj][h][i]

    const int t  = threadIdx.x;
    const int i0 = blockIdx.x * TI;

    // produce ids: fixed (i, h), half of the 32-j chunk
    const int iP = t & 15, hP = (t >> 4) & 7, half = t >> 7;
    // consume ids: warp = head, lane = feature
    const int hC = t >> 5, lane = t & 31;

    u64 pl2;
    {
        float2 v = PLC_buf[(i0 + iP) * NH + hP];
        PACK2(pl2, __float_as_uint(v.x), __float_as_uint(v.y));
    }
    const int* adjrow = &adj[(size_t)(i0 + iP) * N_NODES + half * 16];
    const float2* prbase = &PRC_buf[half * 16 * NH + hP];
    float zp = 0.f;

    const float* grow = &g_buf[hC * 32 + lane];
    unsigned wsb = (unsigned)__cvta_generic_to_shared(&w_sh[0][0][hC][0]);
    u64 acc[8];
#pragma unroll
    for (int k = 0; k < 8; k++) acc[k] = 0ull;
    float gA[16], gB[16];
#pragma unroll
    for (int jj = 0; jj < 16; jj++) gA[jj] = grow[jj * 256];   // chunk0 half0

    // ---- produce(chunk, buf) as a lambda-ish macro body ----
#define PRODUCE(CHUNK, B)                                                     \
    {                                                                         \
        int _j0 = (CHUNK) * JC;                                               \
        const float2* _prc = prbase + (size_t)_j0 * NH;                       \
        int4 _a0 = *(const int4*)&adjrow[(CHUNK) * JC + 0];                   \
        int4 _a1 = *(const int4*)&adjrow[(CHUNK) * JC + 4];                   \
        int4 _a2 = *(const int4*)&adjrow[(CHUNK) * JC + 8];                   \
        int4 _a3 = *(const int4*)&adjrow[(CHUNK) * JC + 12];                  \
        int _av[16] = {_a0.x,_a0.y,_a0.z,_a0.w, _a1.x,_a1.y,_a1.z,_a1.w,      \
                       _a2.x,_a2.y,_a2.z,_a2.w, _a3.x,_a3.y,_a3.z,_a3.w};     \
        float* _wdst = &w_sh[B][half * 16][hP][iP];                           \
        _Pragma("unroll")                                                     \
        for (int k = 0; k < 16; k++) {                                        \
            float2 _pv = _prc[k * NH];                                        \
            u64 _pr2; PACK2(_pr2, __float_as_uint(_pv.x), __float_as_uint(_pv.y)); \
            u64 _m; MUL2(_m, pl2, _pr2);                                      \
            unsigned _lo, _hi; UNPACK2(_lo, _hi, _m);                         \
            float _w = fmaxf(__uint_as_float(_lo), __uint_as_float(_hi));     \
            _w = _av[k] ? _w : 0.f;                                           \
            zp += _w;                                                         \
            _wdst[k * (NH * 16)] = _w;                                        \
        }                                                                     \
    }

    PRODUCE(0, 0)                       // prime chunk 0 into buffer 0
    __syncthreads();

    int buf = 0;
    for (int c = 0; c < NCHUNK; c++) {
        int nbuf = buf + 1; if (nbuf == 3) nbuf = 0;
        if (c + 1 < NCHUNK) PRODUCE(c + 1, nbuf)
        __syncthreads();

        // ---- consume chunk c from buffer buf ----
        int j0 = c * JC;
        unsigned wb = wsb + buf * (JC * NH * 16 * 4);
#pragma unroll
        for (int jj = 0; jj < 16; jj++) gB[jj] = grow[(j0 + 16 + jj) * 256];
#pragma unroll
        for (int jj = 0; jj < 16; jj++) {
            unsigned gu = __float_as_uint(gA[jj]);
            u64 gd; PACK2(gd, gu, gu);
            unsigned wa = wb + jj * (NH * 16 * 4);
            u64 w0, w1, w2, w3, w4, w5, w6, w7;
            LDSV2(w0, w1, wa);
            LDSV2(w2, w3, wa + 16);
            LDSV2(w4, w5, wa + 32);
            LDSV2(w6, w7, wa + 48);
            FMA2(acc[0], gd, w0, acc[0]);
            FMA2(acc[1], gd, w1, acc[1]);
            FMA2(acc[2], gd, w2, acc[2]);
            FMA2(acc[3], gd, w3, acc[3]);
            FMA2(acc[4], gd, w4, acc[4]);
            FMA2(acc[5], gd, w5, acc[5]);
            FMA2(acc[6], gd, w6, acc[6]);
            FMA2(acc[7], gd, w7, acc[7]);
        }
        int j0n = (j0 + JC) & (N_NODES - 1);
#pragma unroll
        for (int jj = 0; jj < 16; jj++) gA[jj] = grow[(j0n + jj) * 256];
#pragma unroll
        for (int jj = 0; jj < 16; jj++) {
            unsigned gu = __float_as_uint(gB[jj]);
            u64 gd; PACK2(gd, gu, gu);
            unsigned wa = wb + (16 + jj) * (NH * 16 * 4);
            u64 w0, w1, w2, w3, w4, w5, w6, w7;
            LDSV2(w0, w1, wa);
            LDSV2(w2, w3, wa + 16);
            LDSV2(w4, w5, wa + 32);
            LDSV2(w6, w7, wa + 48);
            FMA2(acc[0], gd, w0, acc[0]);
            FMA2(acc[1], gd, w1, acc[1]);
            FMA2(acc[2], gd, w2, acc[2]);
            FMA2(acc[3], gd, w3, acc[3]);
            FMA2(acc[4], gd, w4, acc[4]);
            FMA2(acc[5], gd, w5, acc[5]);
            FMA2(acc[6], gd, w6, acc[6]);
            FMA2(acc[7], gd, w7, acc[7]);
        }
        buf = nbuf;
    }

    // ---- z reduction through w_sh (freed), then normalize + store ----
    __syncthreads();
    float* zs = &w_sh[0][0][0][0];
    zs[(iP * NH + hP) * 2 + half] = zp;
    __syncthreads();

#pragma unroll
    for (int k = 0; k < 8; k++) {
        float2 v = *(float2*)&acc[k];
        int ia = 2 * k, ib = 2 * k + 1;
        float za = zs[(ia * NH + hC) * 2] + zs[(ia * NH + hC) * 2 + 1];
        float zb = zs[(ib * NH + hC) * 2] + zs[(ib * NH + hC) * 2 + 1];
        out[(i0 + ia) * 256 + hC * 32 + lane] = __fdividef(v.x, za);
        out[(i0 + ib) * 256 + hC * 32 + lane] = __fdividef(v.y, zb);
    }
#undef PRODUCE
}

// ---------------------------------------------------------------------------
extern "C" void kernel_launch(void* const* d_in, const int* in_sizes, int n_in,
                              void* d_out, int out_size) {
    const float* H   = (const float*)d_in[0];
    const float* W   = (const float*)d_in[1];
    const float* a   = (const float*)d_in[2];
    const int*   adj = (const int*)d_in[3];
    float*       out = (float*)d_out;

    dim3 gg(OUTF / 64, N_NODES / 64);
    gemm_kernel<<<gg, 256>>>(H, W);
    score_kernel<<<N_NODES / 8, 256>>>(a);
    attn_kernel<<<N_NODES / TI, 256>>>(adj, out);
}

// round 10
// speedup vs baseline: 1.0032x; 1.0032x over previous
#include <cuda_runtime.h>
#include <cstdint>

#define N_NODES 4096
#define OUTF 256
#define NH 8
#define TI 16
#define JC 32
#define NCHUNK (N_NODES / JC)

typedef unsigned long long u64;

// Scratch (device globals — no allocation allowed)
__device__ float  g_buf[N_NODES * OUTF];      // g = h @ W^T, [n][h*32+f]
__device__ float2 PLC_buf[N_NODES * NH];      // {exp(s_i), exp(0.2 s_i)}
__device__ float2 PRC_buf[N_NODES * NH];      // {exp(s_j), exp(0.2 s_j)}

#define PACK2(d, lo, hi) asm("mov.b64 %0, {%1, %2};" : "=l"(d) : "r"(lo), "r"(hi))
#define UNPACK2(lo, hi, s) asm("mov.b64 {%0, %1}, %2;" : "=r"(lo), "=r"(hi) : "l"(s))
#define FMA2(d, a, b, c) asm("fma.rn.f32x2 %0, %1, %2, %3;" : "=l"(d) : "l"(a), "l"(b), "l"(c))
#define MUL2(d, a, b) asm("mul.rn.f32x2 %0, %1, %2;" : "=l"(d) : "l"(a), "l"(b))
#define LDSV2(a, b, addr) asm volatile("ld.shared.v2.b64 {%0,%1},[%2];" : "=l"(a), "=l"(b) : "r"(addr))

// ---------------------------------------------------------------------------
// Kernel 1: g = h @ W^T   (4096x256 @ 256x256)
// ---------------------------------------------------------------------------
__global__ __launch_bounds__(256) void gemm_kernel(const float* __restrict__ H,
                                                   const float* __restrict__ W) {
    __shared__ float hs[64][32];
    __shared__ float ws[32][68];
    int t  = threadIdx.x;
    int bo = blockIdx.x;
    int bn = blockIdx.y;
    int tx = t & 15, ty = t >> 4;
    float acc[4][4] = {};

    int r = t >> 3, c = (t & 7) << 2;
    for (int k0 = 0; k0 < 256; k0 += 32) {
#pragma unroll
        for (int rr = 0; rr < 64; rr += 32) {
            float4 v = *(const float4*)&H[(bn * 64 + r + rr) * 256 + k0 + c];
            *(float4*)&hs[r + rr][c] = v;
        }
#pragma unroll
        for (int oo = 0; oo < 64; oo += 32) {
            float4 v = *(const float4*)&W[(bo * 64 + r + oo) * 256 + k0 + c];
            ws[c + 0][r + oo] = v.x; ws[c + 1][r + oo] = v.y;
            ws[c + 2][r + oo] = v.z; ws[c + 3][r + oo] = v.w;
        }
        __syncthreads();
#pragma unroll
        for (int k = 0; k < 32; k++) {
            float4 bv = *(const float4*)&ws[k][tx * 4];
            const float* bp = &bv.x;
            float av[4];
#pragma unroll
            for (int i = 0; i < 4; i++) av[i] = hs[ty * 4 + i][k];
#pragma unroll
            for (int i = 0; i < 4; i++)
#pragma unroll
                for (int j = 0; j < 4; j++)
                    acc[i][j] = fmaf(av[i], bp[j], acc[i][j]);
        }
        __syncthreads();
    }
#pragma unroll
    for (int i = 0; i < 4; i++) {
        float4 v = make_float4(acc[i][0], acc[i][1], acc[i][2], acc[i][3]);
        *(float4*)&g_buf[(bn * 64 + ty * 4 + i) * 256 + bo * 64 + tx * 4] = v;
    }
}

// ---------------------------------------------------------------------------
// Kernel 2: per-node scores -> compact {E, F} exponential tables.
// ---------------------------------------------------------------------------
__global__ __launch_bounds__(256) void score_kernel(const float* __restrict__ a) {
    int gw   = (blockIdx.x * 256 + threadIdx.x) >> 5;
    int lane = threadIdx.x & 31;
    if (gw >= N_NODES) return;
    float al = a[lane], ar = a[32 + lane];
#pragma unroll
    for (int h = 0; h < NH; h++) {
        float gv = g_buf[gw * 256 + h * 32 + lane];
        float sl = gv * al, sr = gv * ar;
#pragma unroll
        for (int o = 16; o > 0; o >>= 1) {
            sl += __shfl_xor_sync(0xffffffffu, sl, o);
            sr += __shfl_xor_sync(0xffffffffu, sr, o);
        }
        if (lane == 0) {
            PLC_buf[gw * NH + h] = make_float2(expf(sl), expf(0.2f * sl));
            PRC_buf[gw * NH + h] = make_float2(expf(sr), expf(0.2f * sr));
        }
    }
}

// ---------------------------------------------------------------------------
// Kernel 3: fused masked-softmax attention + aggregation.
// Uniform warps, 3-buffer ring, one __syncthreads per chunk.
// Produce role (per thread, fixed i,h, half of the jj range):
//   w = adj ? max(E_i E_j, F_i F_j) : 0   via one mul.rn.f32x2 + FMNMX.
// Consume role (warp = head, lane = feature): packed f32x2 FMAs, g pipelined
// through register halves, 128-bit broadcast shared loads of w.
// ---------------------------------------------------------------------------
__global__ __launch_bounds__(256, 2) void attn_kernel(const int* __restrict__ adj,
                                                      float* __restrict__ out) {
    __shared__ float w_sh[3][JC][NH][16];   // 48KB exactly; [buf][jj][h][i]

    const int t  = threadIdx.x;
    const int i0 = blockIdx.x * TI;

    // produce ids: fixed (i, h), half of the 32-j chunk
    const int iP = t & 15, hP = (t >> 4) & 7, half = t >> 7;
    // consume ids: warp = head, lane = feature
    const int hC = t >> 5, lane = t & 31;

    u64 pl2;
    {
        float2 v = PLC_buf[(i0 + iP) * NH + hP];
        PACK2(pl2, __float_as_uint(v.x), __float_as_uint(v.y));
    }
    const int* adjrow = &adj[(size_t)(i0 + iP) * N_NODES + half * 16];
    const float2* prbase = &PRC_buf[half * 16 * NH + hP];
    float zp = 0.f;

    const float* grow = &g_buf[hC * 32 + lane];
    unsigned wsb = (unsigned)__cvta_generic_to_shared(&w_sh[0][0][hC][0]);
    u64 acc[8];
#pragma unroll
    for (int k = 0; k < 8; k++) acc[k] = 0ull;
    float gA[16], gB[16];
#pragma unroll
    for (int jj = 0; jj < 16; jj++) gA[jj] = grow[jj * 256];   // chunk0 half0

    // ---- produce(chunk, buf) as a lambda-ish macro body ----
#define PRODUCE(CHUNK, B)                                                     \
    {                                                                         \
        int _j0 = (CHUNK) * JC;                                               \
        const float2* _prc = prbase + (size_t)_j0 * NH;                       \
        int4 _a0 = *(const int4*)&adjrow[(CHUNK) * JC + 0];                   \
        int4 _a1 = *(const int4*)&adjrow[(CHUNK) * JC + 4];                   \
        int4 _a2 = *(const int4*)&adjrow[(CHUNK) * JC + 8];                   \
        int4 _a3 = *(const int4*)&adjrow[(CHUNK) * JC + 12];                  \
        int _av[16] = {_a0.x,_a0.y,_a0.z,_a0.w, _a1.x,_a1.y,_a1.z,_a1.w,      \
                       _a2.x,_a2.y,_a2.z,_a2.w, _a3.x,_a3.y,_a3.z,_a3.w};     \
        float* _wdst = &w_sh[B][half * 16][hP][iP];                           \
        _Pragma("unroll")                                                     \
        for (int k = 0; k < 16; k++) {                                        \
            float2 _pv = _prc[k * NH];                                        \
            u64 _pr2; PACK2(_pr2, __float_as_uint(_pv.x), __float_as_uint(_pv.y)); \
            u64 _m; MUL2(_m, pl2, _pr2);                                      \
            unsigned _lo, _hi; UNPACK2(_lo, _hi, _m);                         \
            float _w = fmaxf(__uint_as_float(_lo), __uint_as_float(_hi));     \
            _w = _av[k] ? _w : 0.f;                                           \
            zp += _w;                                                         \
            _wdst[k * (NH * 16)] = _w;                                        \
        }                                                                     \
    }

    PRODUCE(0, 0)                       // prime chunk 0 into buffer 0
    __syncthreads();

    int buf = 0;
    for (int c = 0; c < NCHUNK; c++) {
        int nbuf = buf + 1; if (nbuf == 3) nbuf = 0;
        if (c + 1 < NCHUNK) PRODUCE(c + 1, nbuf)
        __syncthreads();

        // ---- consume chunk c from buffer buf ----
        int j0 = c * JC;
        unsigned wb = wsb + buf * (JC * NH * 16 * 4);
#pragma unroll
        for (int jj = 0; jj < 16; jj++) gB[jj] = grow[(j0 + 16 + jj) * 256];
#pragma unroll
        for (int jj = 0; jj < 16; jj++) {
            unsigned gu = __float_as_uint(gA[jj]);
            u64 gd; PACK2(gd, gu, gu);
            unsigned wa = wb + jj * (NH * 16 * 4);
            u64 w0, w1, w2, w3, w4, w5, w6, w7;
            LDSV2(w0, w1, wa);
            LDSV2(w2, w3, wa + 16);
            LDSV2(w4, w5, wa + 32);
            LDSV2(w6, w7, wa + 48);
            FMA2(acc[0], gd, w0, acc[0]);
            FMA2(acc[1], gd, w1, acc[1]);
            FMA2(acc[2], gd, w2, acc[2]);
            FMA2(acc[3], gd, w3, acc[3]);
            FMA2(acc[4], gd, w4, acc[4]);
            FMA2(acc[5], gd, w5, acc[5]);
            FMA2(acc[6], gd, w6, acc[6]);
            FMA2(acc[7], gd, w7, acc[7]);
        }
        int j0n = (j0 + JC) & (N_NODES - 1);
#pragma unroll
        for (int jj = 0; jj < 16; jj++) gA[jj] = grow[(j0n + jj) * 256];
#pragma unroll
        for (int jj = 0; jj < 16; jj++) {
            unsigned gu = __float_as_uint(gB[jj]);
            u64 gd; PACK2(gd, gu, gu);
            unsigned wa = wb + (16 + jj) * (NH * 16 * 4);
            u64 w0, w1, w2, w3, w4, w5, w6, w7;
            LDSV2(w0, w1, wa);
            LDSV2(w2, w3, wa + 16);
            LDSV2(w4, w5, wa + 32);
            LDSV2(w6, w7, wa + 48);
            FMA2(acc[0], gd, w0, acc[0]);
            FMA2(acc[1], gd, w1, acc[1]);
            FMA2(acc[2], gd, w2, acc[2]);
            FMA2(acc[3], gd, w3, acc[3]);
            FMA2(acc[4], gd, w4, acc[4]);
            FMA2(acc[5], gd, w5, acc[5]);
            FMA2(acc[6], gd, w6, acc[6]);
            FMA2(acc[7], gd, w7, acc[7]);
        }
        buf = nbuf;
    }

    // ---- z reduction through w_sh (freed), then normalize + store ----
    __syncthreads();
    float* zs = &w_sh[0][0][0][0];
    zs[(iP * NH + hP) * 2 + half] = zp;
    __syncthreads();

#pragma unroll
    for (int k = 0; k < 8; k++) {
        float2 v = *(float2*)&acc[k];
        int ia = 2 * k, ib = 2 * k + 1;
        float za = zs[(ia * NH + hC) * 2] + zs[(ia * NH + hC) * 2 + 1];
        float zb = zs[(ib * NH + hC) * 2] + zs[(ib * NH + hC) * 2 + 1];
        out[(i0 + ia) * 256 + hC * 32 + lane] = __fdividef(v.x, za);
        out[(i0 + ib) * 256 + hC * 32 + lane] = __fdividef(v.y, zb);
    }
#undef PRODUCE
}

// ---------------------------------------------------------------------------
extern "C" void kernel_launch(void* const* d_in, const int* in_sizes, int n_in,
                              void* d_out, int out_size) {
    const float* H   = (const float*)d_in[0];
    const float* W   = (const float*)d_in[1];
    const float* a   = (const float*)d_in[2];
    const int*   adj = (const int*)d_in[3];
    float*       out = (float*)d_out;

    dim3 gg(OUTF / 64, N_NODES / 64);
    gemm_kernel<<<gg, 256>>>(H, W);
    score_kernel<<<N_NODES / 8, 256>>>(a);
    attn_kernel<<<N_NODES / TI, 256>>>(adj, out);
}